// round 16
// baseline (speedup 1.0000x reference)
#include <cuda_runtime.h>

#define NG 16
#define NBATCH 64
#define INV224 (1.0f / 224.0f)

static const int NA0 = 37632;   // 3*112*112
static const int NA1 = 9408;    // 3*56*56
static const int NA2 = 2352;    // 3*28*28
static const int NBX0 = 21, NBa1 = 10, NBa2 = 3;

// scratch: [scale][image][anchor]; -1 sentinel for non-negatives
static __device__ float g_bce[3161088];
static __device__ int   g_hist[192 * 2048];
static __device__ float g_posbce[192];
static __device__ float g_cls[192];
static __device__ float g_loc[192];
static __device__ int   g_npos[192];
static __device__ int   g_navail[192];
static __device__ float g_tot[3];
static __device__ int   g_done;
// phaseB cooperative state
static __device__ float g_buf[192 * 4096];
static __device__ float g_psum[192];
static __device__ int   g_bcnt[192];
static __device__ int   g_arr[192];

// ---------------- Phase A epilogue ----------------

__device__ __forceinline__ void flush_block(int* s_h, int* hrow, int acc,
                                            int s_np, int s_nv,
                                            float s_pb, float s_cl, float s_lo, int t)
{
    #pragma unroll
    for (int i = 0; i < 8; i++) {
        int c = s_h[t + i * 256];
        if (c) atomicAdd(&hrow[t + i * 256], c);
    }
    if (t == 0) {
        if (s_np) {
            atomicAdd(&g_npos[acc],   s_np);
            atomicAdd(&g_posbce[acc], s_pb);
            atomicAdd(&g_cls[acc],    s_cl);
            atomicAdd(&g_loc[acc],    s_lo);
        }
        if (s_nv) atomicAdd(&g_navail[acc], s_nv);
    }
}

// ---------------- Phase A: scale-0 separable path, analytic anchors ----------------

__device__ void scale0_path(const float* __restrict__ p,
                            const float* __restrict__ tb,
                            const int*   __restrict__ tl,
                            int bi, int b, int* s_h)
{
    constexpr int H = 112, HH = H * H;
    __shared__ __align__(16) float s_iwS[16 * H];
    __shared__ __align__(16) float s_ih[16 * 16];
    __shared__ float s_invS[16];
    __shared__ float stb0[64];
    __shared__ int   stl0[16];
    __shared__ float z_pb, z_cl, z_lo;
    __shared__ int   z_np, z_nv;

    const int t = threadIdx.x;
    const int a = bi / 7;
    const int row0 = (bi - a * 7) * 16;
    const float sz = 16.0f + 8.0f * (float)a;
    const float h2 = 0.5f * sz;

    if (t < 64) stb0[t] = tb[b * 64 + t] * INV224;
    if (t < 16) stl0[t] = tl[b * 16 + t];
    if (t == 0) { z_pb = 0.f; z_cl = 0.f; z_lo = 0.f; z_np = 0; z_nv = 0; }
    #pragma unroll
    for (int i = 0; i < 8; i++) s_h[t + i * 256] = 0;
    __syncthreads();

    if (t < 16) {
        float areaB = (stb0[t * 4 + 2] - stb0[t * 4 + 0]) * (stb0[t * 4 + 3] - stb0[t * 4 + 1]);
        float a1 = (1.0f - h2) * INV224, a2 = (1.0f + h2) * INV224;
        float wn = a2 - a1;
        s_invS[t] = __fdividef(1.0f, wn * wn + areaB);
    }
    __syncthreads();

    for (int e = t; e < 16 * H; e += 256) {
        int g = e / H, x = e - g * H;
        float cx = (x + 0.5f) * 2.0f;
        float ax1 = (cx - h2) * INV224, ax2 = (cx + h2) * INV224;
        float lx = fmaxf(ax1, stb0[g * 4 + 0]);
        float rx = fminf(ax2, stb0[g * 4 + 2]);
        s_iwS[e] = fmaxf(rx - lx, 0.f) * s_invS[g];
    }
    {
        int g = t >> 4, rr = t & 15;
        float cy = (row0 + rr + 0.5f) * 2.0f;
        float ay1 = (cy - h2) * INV224, ay2 = (cy + h2) * INV224;
        float ly = fmaxf(ay1, stb0[g * 4 + 1]);
        float ry = fminf(ay2, stb0[g * 4 + 3]);
        s_ih[g * 16 + rr] = fmaxf(ry - ly, 0.f);
    }
    __syncthreads();

    const bool active = t < 224;
    const int x  = active ? (t % H) : 0;
    const int rg = active ? (t / H) : 0;

    float best[8];
    #pragma unroll
    for (int j = 0; j < 8; j++) best[j] = 0.f;
    if (active) {
        #pragma unroll
        for (int g = 0; g < 16; g++) {
            const float iwS = s_iwS[g * H + x];
            const float4 i0 = *(const float4*)&s_ih[g * 16 + rg * 8];
            const float4 i1 = *(const float4*)&s_ih[g * 16 + rg * 8 + 4];
            best[0] = fmaxf(best[0], iwS * i0.x);
            best[1] = fmaxf(best[1], iwS * i0.y);
            best[2] = fmaxf(best[2], iwS * i0.z);
            best[3] = fmaxf(best[3], iwS * i0.w);
            best[4] = fmaxf(best[4], iwS * i1.x);
            best[5] = fmaxf(best[5], iwS * i1.y);
            best[6] = fmaxf(best[6], iwS * i1.z);
            best[7] = fmaxf(best[7], iwS * i1.w);
        }
    }

    int cnt_p = 0, cnt_n = 0;
    if (active) {
        #pragma unroll
        for (int j = 0; j < 8; j++) {
            const float bj = best[j];
            const bool pos = 3.0f * bj >= 1.0f;
            const bool neg = 3.5f * bj <  1.0f;
            cnt_p += pos; cnt_n += neg;

            const int y = row0 + rg * 8 + j;
            const int rem = y * H + x;
            const int n = a * HH + rem;
            const float* base = p + (((long)b * 3 + a) * 8) * (long)HH + rem;

            const float o = base[(long)4 * HH];
            const float bce = fmaxf(o, 0.f) - (pos ? o : 0.f) + __logf(1.0f + __expf(-fabsf(o)));

            g_bce[(long)b * NA0 + n] = neg ? bce : -1.0f;
            if (neg) atomicAdd(&s_h[(int)(__float_as_uint(bce) >> 20)], 1);

            if (pos) {
                int gi = 0; float bb = -1.f;
                #pragma unroll
                for (int g = 0; g < 16; g++) {
                    float sc = s_iwS[g * H + x] * s_ih[g * 16 + rg * 8 + j];
                    if (sc > bb) { bb = sc; gi = g; }
                }
                atomicAdd(&z_pb, bce);
                float cxA = (x + 0.5f) * 2.0f, cyA = (y + 0.5f) * 2.0f;
                float ax1 = (cxA - h2) * INV224, ay1 = (cyA - h2) * INV224;
                float ax2 = (cxA + h2) * INV224, ay2 = (cyA + h2) * INV224;
                float aw = ax2 - ax1, ah = ay2 - ay1;
                float mx1 = stb0[gi * 4 + 0], my1 = stb0[gi * 4 + 1];
                float mx2 = stb0[gi * 4 + 2], my2 = stb0[gi * 4 + 3];
                float gcx = 0.5f * (mx1 + mx2), gcy = 0.5f * (my1 + my2);
                float gw = mx2 - mx1, gh = my2 - my1;
                float acx = 0.5f * (ax1 + ax2), acy = 0.5f * (ay1 + ay2);
                float e0 = __fdividef(gcx - acx, aw);
                float e1 = __fdividef(gcy - acy, ah);
                float e2 = __logf(__fdividef(gw, aw) + 1e-6f);
                float e3 = __logf(__fdividef(gh, ah) + 1e-6f);
                float d0 = base[0]            - e0;
                float d1 = base[(long)1 * HH] - e1;
                float d2 = base[(long)2 * HH] - e2;
                float d3 = base[(long)3 * HH] - e3;
                #define SL1_(d) (fabsf(d) < 1.f ? 0.5f * (d) * (d) : fabsf(d) - 0.5f)
                atomicAdd(&z_lo, SL1_(d0) + SL1_(d1) + SL1_(d2) + SL1_(d3));
                #undef SL1_
                float zv0 = base[(long)5 * HH];
                float zv1 = base[(long)6 * HH];
                float zv2 = base[(long)7 * HH];
                float m = fmaxf(zv0, fmaxf(zv1, zv2));
                float lse = m + __logf(__expf(zv0 - m) + __expf(zv1 - m) + __expf(zv2 - m));
                int ml = stl0[gi];
                float zl = (ml == 1) ? zv0 : ((ml == 2) ? zv1 : zv2);
                atomicAdd(&z_cl, lse - zl);
            }
        }
    }

    unsigned wp = __reduce_add_sync(0xffffffff, (unsigned)cnt_p);
    unsigned wn = __reduce_add_sync(0xffffffff, (unsigned)cnt_n);
    if ((t & 31) == 0) {
        if (wp) atomicAdd(&z_np, (int)wp);
        if (wn) atomicAdd(&z_nv, (int)wn);
    }
    __syncthreads();
    flush_block(s_h, &g_hist[b * 2048], b, z_np, z_nv, z_pb, z_cl, z_lo, t);
}

// ---------------- Phase A: generic path (scales 1,2), analytic anchors ----------------

template<int H, int NA, int ACCB, long SCRB, int SB_, int SS_>
__device__ __forceinline__ void phaseA_impl(const float* __restrict__ p,
                                            const float* __restrict__ tb,
                                            const int*   __restrict__ tl,
                                            int bs, int b, int* s_h)
{
    constexpr int HH = H * H;
    constexpr float STRIDE = 224.0f / H;
    __shared__ float stb[NG * 4];
    __shared__ float sarea[NG];
    __shared__ int   stl[NG];
    __shared__ float s_pb, s_cl, s_lo;
    __shared__ int   s_np, s_nv;

    const int t = threadIdx.x;
    if (t < NG * 4) stb[t] = tb[b * NG * 4 + t] * INV224;
    if (t < NG)     stl[t] = tl[b * NG + t];
    if (t == 0) { s_pb = 0.f; s_cl = 0.f; s_lo = 0.f; s_np = 0; s_nv = 0; }
    #pragma unroll
    for (int i = 0; i < 8; i++) s_h[t + i * 256] = 0;
    __syncthreads();
    if (t < NG) sarea[t] = (stb[t * 4 + 2] - stb[t * 4 + 0]) * (stb[t * 4 + 3] - stb[t * 4 + 1]);
    __syncthreads();

    const int n0 = bs * 1024 + t;

    float ax1[4], ay1[4], ax2[4], ay2[4], area[4];
    bool  act[4];
    #pragma unroll
    for (int j = 0; j < 4; j++) {
        const int n = n0 + j * 256;
        act[j] = (n < NA);
        if (act[j]) {
            const int a = n / HH;
            const int rem = n - a * HH;
            const int y = rem / H, x = rem - y * H;
            const float szf = (float)SB_ + (float)SS_ * (float)a;
            const float h2 = 0.5f * szf;
            const float cx = (x + 0.5f) * STRIDE, cy = (y + 0.5f) * STRIDE;
            ax1[j] = (cx - h2) * INV224; ay1[j] = (cy - h2) * INV224;
            ax2[j] = (cx + h2) * INV224; ay2[j] = (cy + h2) * INV224;
            area[j] = (ax2[j] - ax1[j]) * (ay2[j] - ay1[j]);
        } else {
            ax1[j] = 0.f; ay1[j] = 0.f; ax2[j] = 0.f; ay2[j] = 0.f; area[j] = 0.f;
        }
    }

    float bestI[4], bestD[4]; int bi[4];
    #pragma unroll
    for (int j = 0; j < 4; j++) { bestI[j] = -1.f; bestD[j] = 1.f; bi[j] = 0; }

    #pragma unroll
    for (int g = 0; g < NG; g++) {
        const float bx1 = stb[g * 4 + 0], by1 = stb[g * 4 + 1];
        const float bx2 = stb[g * 4 + 2], by2 = stb[g * 4 + 3];
        const float ba  = sarea[g];
        #pragma unroll
        for (int j = 0; j < 4; j++) {
            float lx = fmaxf(ax1[j], bx1), ly = fmaxf(ay1[j], by1);
            float rx = fminf(ax2[j], bx2), ry = fminf(ay2[j], by2);
            float iw = fmaxf(rx - lx, 0.f), ih = fmaxf(ry - ly, 0.f);
            float inter = iw * ih;
            float den = area[j] + ba - inter + 1e-9f;
            if (inter * bestD[j] > bestI[j] * den) { bestI[j] = inter; bestD[j] = den; bi[j] = g; }
        }
    }

    int cnt_p = 0, cnt_n = 0;

    #pragma unroll
    for (int j = 0; j < 4; j++) {
        const int n = n0 + j * 256;
        if (act[j]) {
            const bool pos = bestI[j] >= 0.5f * bestD[j];
            const bool neg = bestI[j] <  0.4f * bestD[j];
            cnt_p += pos; cnt_n += neg;

            const int a = n / HH;
            const int rem = n - a * HH;
            const float* base = p + (((long)b * 3 + a) * 8) * (long)HH + rem;

            const float o = base[(long)4 * HH];
            const float bce = fmaxf(o, 0.f) - (pos ? o : 0.f) + __logf(1.0f + __expf(-fabsf(o)));

            g_bce[SCRB + (long)b * NA + n] = neg ? bce : -1.0f;
            if (neg) atomicAdd(&s_h[(int)(__float_as_uint(bce) >> 20)], 1);

            if (pos) {
                atomicAdd(&s_pb, bce);
                const int gi = bi[j];
                float mx1 = stb[gi * 4 + 0], my1 = stb[gi * 4 + 1];
                float mx2 = stb[gi * 4 + 2], my2 = stb[gi * 4 + 3];
                float gcx = 0.5f * (mx1 + mx2), gcy = 0.5f * (my1 + my2);
                float gw = mx2 - mx1, gh = my2 - my1;
                float aw = ax2[j] - ax1[j], ah = ay2[j] - ay1[j];
                float acx = 0.5f * (ax1[j] + ax2[j]), acy = 0.5f * (ay1[j] + ay2[j]);
                float e0 = __fdividef(gcx - acx, aw);
                float e1 = __fdividef(gcy - acy, ah);
                float e2 = __logf(__fdividef(gw, aw) + 1e-6f);
                float e3 = __logf(__fdividef(gh, ah) + 1e-6f);
                float d0 = base[0]            - e0;
                float d1 = base[(long)1 * HH] - e1;
                float d2 = base[(long)2 * HH] - e2;
                float d3 = base[(long)3 * HH] - e3;
                #define SL1_(d) (fabsf(d) < 1.f ? 0.5f * (d) * (d) : fabsf(d) - 0.5f)
                atomicAdd(&s_lo, SL1_(d0) + SL1_(d1) + SL1_(d2) + SL1_(d3));
                #undef SL1_
                float z0 = base[(long)5 * HH];
                float z1 = base[(long)6 * HH];
                float z2 = base[(long)7 * HH];
                float m = fmaxf(z0, fmaxf(z1, z2));
                float lse = m + __logf(__expf(z0 - m) + __expf(z1 - m) + __expf(z2 - m));
                int ml = stl[gi];
                float zl = (ml == 1) ? z0 : ((ml == 2) ? z1 : z2);
                atomicAdd(&s_cl, lse - zl);
            }
        }
    }

    unsigned wp = __reduce_add_sync(0xffffffff, (unsigned)cnt_p);
    unsigned wn = __reduce_add_sync(0xffffffff, (unsigned)cnt_n);
    if ((t & 31) == 0) {
        if (wp) atomicAdd(&s_np, (int)wp);
        if (wn) atomicAdd(&s_nv, (int)wn);
    }
    __syncthreads();
    flush_block(s_h, &g_hist[(ACCB + b) * 2048], ACCB + b, s_np, s_nv, s_pb, s_cl, s_lo, t);
}

__global__ void __launch_bounds__(256) k_phaseA(const float* __restrict__ p0,
                                                const float* __restrict__ p1,
                                                const float* __restrict__ p2,
                                                const float* __restrict__ tb,
                                                const int*   __restrict__ tl)
{
    __shared__ int s_h[2048];
    const int bx = blockIdx.x, b = blockIdx.y;
    if (bx < NBX0)             scale0_path(p0, tb, tl, bx, b, s_h);
    else if (bx < NBX0 + NBa1) phaseA_impl<56, NA1, 64,  2408448L, 48, 16>(p1, tb, tl, bx - NBX0, b, s_h);
    else                       phaseA_impl<28, NA2, 128, 3010560L, 96, 32>(p2, tb, tl, bx - NBX0 - NBa1, b, s_h);
}

// ---------------- Phase B: cooperative multi-block selection ----------------

__device__ __forceinline__ void select1024(const int* hist, int k, int t, int lane,
                                           int wid, int* s_w, int* sT, int* sKr)
{
    int c = hist[1023 - t];
    int v = c;
    #pragma unroll
    for (int o = 1; o < 32; o <<= 1) { int u = __shfl_up_sync(~0u, v, o); if (lane >= o) v += u; }
    if (lane == 31) s_w[wid] = v;
    __syncthreads();
    if (wid == 0) {
        int w = s_w[lane];
        #pragma unroll
        for (int o = 1; o < 32; o <<= 1) { int u = __shfl_up_sync(~0u, w, o); if (lane >= o) w += u; }
        s_w[lane] = w;
    }
    __syncthreads();
    int incl = v + (wid ? s_w[wid - 1] : 0);
    int excl = incl - c;
    if (excl < k && k <= incl) { *sT = 1023 - t; *sKr = k - excl; }
    __syncthreads();
}

__global__ void __launch_bounds__(1024) k_phaseB(float* __restrict__ out)
{
    const int bid = blockIdx.x;   // 0..383
    int slice, part, nparts;
    if (bid < 256)      { slice = bid >> 2;        part = bid & 3; nparts = 4; }
    else if (bid < 320) { slice = 64 + bid - 256;  part = 0;       nparts = 1; }
    else                { slice = 128 + bid - 320; part = 0;       nparts = 1; }

    const int scale = slice >> 6;
    const int b = slice & 63;
    const int Na   = (scale == 0) ? NA0 : ((scale == 1) ? NA1 : NA2);
    const long off = ((scale == 0) ? 0L : ((scale == 1) ? 2408448L : 3010560L)) + (long)b * Na;
    const int t = threadIdx.x, lane = t & 31, wid = t >> 5;
    const int npos = g_npos[slice];
    const int navail = g_navail[slice];

    __shared__ int   s_w[32];
    __shared__ float s_fw[32];
    __shared__ int   s_hist[1024];
    __shared__ float s_buf[4096];
    __shared__ int   s_cnt, sT, sKr, s_last;
    __shared__ float s_extra;

    int* hrow = &g_hist[slice * 2048];
    const int k = min(3 * npos, navail);
    const bool havek = (npos > 0 && navail > 0);

    int T = 0, kr = 0, cT = 0;
    bool fits = false;

    if (havek) {
        // level-1 select over 2048 bins (2 bins/thread, from top)
        int c0 = hrow[2047 - 2 * t];
        int c1 = hrow[2046 - 2 * t];
        int v = c0 + c1;
        #pragma unroll
        for (int o = 1; o < 32; o <<= 1) { int u = __shfl_up_sync(~0u, v, o); if (lane >= o) v += u; }
        if (lane == 31) s_w[wid] = v;
        __syncthreads();
        if (wid == 0) {
            int w = s_w[lane];
            #pragma unroll
            for (int o = 1; o < 32; o <<= 1) { int u = __shfl_up_sync(~0u, w, o); if (lane >= o) w += u; }
            s_w[lane] = w;
        }
        if (t == 0) s_extra = 0.f;
        __syncthreads();
        int incl = v + (wid ? s_w[wid - 1] : 0);
        int excl = incl - c0 - c1;
        if (excl < k && k <= incl) {
            if (excl + c0 >= k) { sT = 2047 - 2 * t; sKr = k - excl; }
            else                { sT = 2046 - 2 * t; sKr = k - excl - c0; }
        }
        __syncthreads();
        T = sT; kr = sKr;
        cT = hrow[T];
        fits = (cT <= 4096);

        // scan own part: sum buckets > T, gather bucket T into global buffer
        const float4* p4 = (const float4*)&g_bce[off];
        const int n4 = Na >> 2;
        const int span = n4 / nparts;
        const int i0 = part * span, i1 = i0 + span;
        float partial = 0.f;
        for (int i = i0 + t; i < i1; i += 1024) {
            float4 q = p4[i];
            #pragma unroll
            for (int c = 0; c < 4; c++) {
                float x = (c == 0) ? q.x : (c == 1) ? q.y : (c == 2) ? q.z : q.w;
                unsigned u = __float_as_uint(x);
                if ((int)u >= 0) {
                    int bkt = (int)(u >> 20);
                    if (bkt > T) partial += x;
                    else if (bkt == T && fits) {
                        int pb = atomicAdd(&g_bcnt[slice], 1);
                        g_buf[slice * 4096 + pb] = x;
                    }
                }
            }
        }
        // reduce partial across block, accumulate to per-slice sum
        #pragma unroll
        for (int o = 16; o; o >>= 1) partial += __shfl_down_sync(~0u, partial, o);
        __syncthreads();
        if (lane == 0) s_fw[wid] = partial;
        __syncthreads();
        if (t == 0) {
            float s = 0.f;
            #pragma unroll
            for (int i = 0; i < 32; i++) s += s_fw[i];
            atomicAdd(&g_psum[slice], s);
        }
    }

    // arrive; last part-block continues
    __threadfence();
    __syncthreads();
    if (t == 0) s_last = (atomicAdd(&g_arr[slice], 1) == nparts - 1);
    __syncthreads();
    if (!s_last) return;
    __threadfence();

    float o_val = 0.f;

    if (havek) {
        float partial = 0.f;
        if (fits) {
            // load gathered bucket into smem
            const float* gb = &g_buf[slice * 4096];
            for (int i = t; i < cT; i += 1024) s_buf[i] = gb[i];
            __syncthreads();
            if (kr == cT) {
                for (int i = t; i < cT; i += 1024) partial += s_buf[i];
            } else {
                s_hist[t] = 0;
                __syncthreads();
                for (int i = t; i < cT; i += 1024)
                    atomicAdd(&s_hist[(__float_as_uint(s_buf[i]) >> 10) & 1023], 1);
                __syncthreads();
                select1024(s_hist, kr, t, lane, wid, s_w, &sT, &sKr);
                const int T2 = sT; kr = sKr;
                __syncthreads();
                s_hist[t] = 0;
                __syncthreads();
                for (int i = t; i < cT; i += 1024) {
                    unsigned u = __float_as_uint(s_buf[i]);
                    if (((u >> 10) & 1023) == (unsigned)T2) atomicAdd(&s_hist[u & 1023], 1);
                }
                __syncthreads();
                select1024(s_hist, kr, t, lane, wid, s_w, &sT, &sKr);
                const unsigned thrbits = ((unsigned)T << 20) | ((unsigned)T2 << 10) | (unsigned)sT;
                const int krf = sKr;
                __syncthreads();
                for (int i = t; i < cT; i += 1024) {
                    float x = s_buf[i];
                    if (__float_as_uint(x) > thrbits) partial += x;
                }
                if (t == 0) s_extra = (float)krf * __uint_as_float(thrbits);
            }
            // add per-slice above-bucket sum (from all parts)
            if (t == 0) s_extra += g_psum[slice];
        } else {
            // rare fallback: full global rescan; ignore g_psum
            s_hist[t] = 0;
            __syncthreads();
            for (int i = t; i < Na; i += 1024) {
                unsigned u = __float_as_uint(g_bce[off + i]);
                if ((int)u >= 0 && (int)(u >> 20) == T)
                    atomicAdd(&s_hist[(u >> 10) & 1023], 1);
            }
            __syncthreads();
            select1024(s_hist, kr, t, lane, wid, s_w, &sT, &sKr);
            const int T2 = sT; kr = sKr;
            __syncthreads();
            s_hist[t] = 0;
            __syncthreads();
            const unsigned top22 = ((unsigned)T << 10) | (unsigned)T2;
            for (int i = t; i < Na; i += 1024) {
                unsigned u = __float_as_uint(g_bce[off + i]);
                if ((int)u >= 0 && (u >> 10) == top22)
                    atomicAdd(&s_hist[u & 1023], 1);
            }
            __syncthreads();
            select1024(s_hist, kr, t, lane, wid, s_w, &sT, &sKr);
            const unsigned thrbits = ((unsigned)T << 20) | ((unsigned)T2 << 10) | (unsigned)sT;
            const int krf = sKr;
            __syncthreads();
            for (int i = t; i < Na; i += 1024) {
                float x = g_bce[off + i];
                unsigned u = __float_as_uint(x);
                if ((int)u >= 0 && u > thrbits) partial += x;
            }
            if (t == 0) s_extra = (float)krf * __uint_as_float(thrbits);
        }

        #pragma unroll
        for (int o = 16; o; o >>= 1) partial += __shfl_down_sync(~0u, partial, o);
        __syncthreads();
        if (lane == 0) s_fw[wid] = partial;
        __syncthreads();
        if (t == 0) {
            float s = s_extra;
            #pragma unroll
            for (int i = 0; i < 32; i++) s += s_fw[i];
            o_val = g_posbce[slice] / (float)npos + s / (float)k;
        }
    }

    // cleanup + totals
    hrow[t] = 0;
    hrow[t + 1024] = 0;
    if (t == 0) {
        float c = 0.f, l = 0.f;
        if (npos > 0) {
            c = g_cls[slice] / (float)npos;
            l = g_loc[slice] / (4.0f * (float)npos);
        }
        g_npos[slice] = 0; g_navail[slice] = 0;
        g_posbce[slice] = 0.f; g_cls[slice] = 0.f; g_loc[slice] = 0.f;
        g_psum[slice] = 0.f; g_bcnt[slice] = 0; g_arr[slice] = 0;
        atomicAdd(&g_tot[0], o_val);
        atomicAdd(&g_tot[1], c);
        atomicAdd(&g_tot[2], l);
        __threadfence();
        int done = atomicAdd(&g_done, 1);
        if (done == 191) {
            __threadfence();
            float oo = g_tot[0] / (float)NBATCH;
            float cc = g_tot[1] / (float)NBATCH;
            float ll = g_tot[2] / (float)NBATCH;
            out[0] = oo; out[1] = cc; out[2] = ll; out[3] = oo + cc + ll;
            g_tot[0] = 0.f; g_tot[1] = 0.f; g_tot[2] = 0.f;
            g_done = 0;
        }
    }
}

extern "C" void kernel_launch(void* const* d_in, const int* in_sizes, int n_in,
                              void* d_out, int out_size)
{
    const float* p0 = (const float*)d_in[0];
    const float* p1 = (const float*)d_in[1];
    const float* p2 = (const float*)d_in[2];
    const float* tb = (const float*)d_in[6];
    const int*   tl = (const int*)  d_in[7];

    dim3 gA(NBX0 + NBa1 + NBa2, NBATCH);
    k_phaseA<<<gA, 256>>>(p0, p1, p2, tb, tl);
    k_phaseB<<<384, 1024>>>((float*)d_out);
}

// round 17
// speedup vs baseline: 1.1057x; 1.1057x over previous
#include <cuda_runtime.h>

#define NG 16
#define NBATCH 64
#define INV224 (1.0f / 224.0f)

static const int NA0 = 37632;   // 3*112*112
static const int NA1 = 9408;    // 3*56*56
static const int NA2 = 2352;    // 3*28*28
static const int NBX0 = 21, NBa1 = 10, NBa2 = 3;

// scratch: [scale][image][anchor]; -1 sentinel for non-negatives
static __device__ float g_bce[3161088];
static __device__ int   g_hist[192 * 2048];
static __device__ float g_posbce[192];
static __device__ float g_cls[192];
static __device__ float g_loc[192];
static __device__ int   g_npos[192];
static __device__ int   g_navail[192];
static __device__ float g_tot[3];
static __device__ int   g_done;
// phaseB cooperative state
static __device__ float g_buf[192 * 4096];
static __device__ float g_psum[192];
static __device__ int   g_bcnt[192];
static __device__ int   g_arr[192];

// ---------------- Phase A epilogue ----------------

__device__ __forceinline__ void flush_block(int* s_h, int* hrow, int acc,
                                            int s_np, int s_nv,
                                            float s_pb, float s_cl, float s_lo, int t)
{
    #pragma unroll
    for (int i = 0; i < 8; i++) {
        int c = s_h[t + i * 256];
        if (c) atomicAdd(&hrow[t + i * 256], c);
    }
    if (t == 0) {
        if (s_np) {
            atomicAdd(&g_npos[acc],   s_np);
            atomicAdd(&g_posbce[acc], s_pb);
            atomicAdd(&g_cls[acc],    s_cl);
            atomicAdd(&g_loc[acc],    s_lo);
        }
        if (s_nv) atomicAdd(&g_navail[acc], s_nv);
    }
}

// ---------------- Phase A: scale-0 separable path, analytic anchors ----------------

__device__ void scale0_path(const float* __restrict__ p,
                            const float* __restrict__ tb,
                            const int*   __restrict__ tl,
                            int bi, int b, int* s_h)
{
    constexpr int H = 112, HH = H * H;
    __shared__ __align__(16) float s_iwS[16 * H];
    __shared__ __align__(16) float s_ih[16 * 16];
    __shared__ float s_invS[16];
    __shared__ float stb0[64];
    __shared__ int   stl0[16];
    __shared__ float z_pb, z_cl, z_lo;
    __shared__ int   z_np, z_nv;

    const int t = threadIdx.x;
    const int a = bi / 7;
    const int row0 = (bi - a * 7) * 16;
    const float sz = 16.0f + 8.0f * (float)a;
    const float h2 = 0.5f * sz;

    if (t < 64) stb0[t] = tb[b * 64 + t] * INV224;
    if (t < 16) stl0[t] = tl[b * 16 + t];
    if (t == 0) { z_pb = 0.f; z_cl = 0.f; z_lo = 0.f; z_np = 0; z_nv = 0; }
    #pragma unroll
    for (int i = 0; i < 8; i++) s_h[t + i * 256] = 0;
    __syncthreads();

    if (t < 16) {
        float areaB = (stb0[t * 4 + 2] - stb0[t * 4 + 0]) * (stb0[t * 4 + 3] - stb0[t * 4 + 1]);
        float a1 = (1.0f - h2) * INV224, a2 = (1.0f + h2) * INV224;
        float wn = a2 - a1;
        s_invS[t] = __fdividef(1.0f, wn * wn + areaB);
    }
    __syncthreads();

    for (int e = t; e < 16 * H; e += 256) {
        int g = e / H, x = e - g * H;
        float cx = (x + 0.5f) * 2.0f;
        float ax1 = (cx - h2) * INV224, ax2 = (cx + h2) * INV224;
        float lx = fmaxf(ax1, stb0[g * 4 + 0]);
        float rx = fminf(ax2, stb0[g * 4 + 2]);
        s_iwS[e] = fmaxf(rx - lx, 0.f) * s_invS[g];
    }
    {
        int g = t >> 4, rr = t & 15;
        float cy = (row0 + rr + 0.5f) * 2.0f;
        float ay1 = (cy - h2) * INV224, ay2 = (cy + h2) * INV224;
        float ly = fmaxf(ay1, stb0[g * 4 + 1]);
        float ry = fminf(ay2, stb0[g * 4 + 3]);
        s_ih[g * 16 + rr] = fmaxf(ry - ly, 0.f);
    }
    __syncthreads();

    const bool active = t < 224;
    const int x  = active ? (t % H) : 0;
    const int rg = active ? (t / H) : 0;

    float best[8];
    #pragma unroll
    for (int j = 0; j < 8; j++) best[j] = 0.f;
    if (active) {
        #pragma unroll
        for (int g = 0; g < 16; g++) {
            const float iwS = s_iwS[g * H + x];
            const float4 i0 = *(const float4*)&s_ih[g * 16 + rg * 8];
            const float4 i1 = *(const float4*)&s_ih[g * 16 + rg * 8 + 4];
            best[0] = fmaxf(best[0], iwS * i0.x);
            best[1] = fmaxf(best[1], iwS * i0.y);
            best[2] = fmaxf(best[2], iwS * i0.z);
            best[3] = fmaxf(best[3], iwS * i0.w);
            best[4] = fmaxf(best[4], iwS * i1.x);
            best[5] = fmaxf(best[5], iwS * i1.y);
            best[6] = fmaxf(best[6], iwS * i1.z);
            best[7] = fmaxf(best[7], iwS * i1.w);
        }
    }

    int cnt_p = 0, cnt_n = 0;
    if (active) {
        #pragma unroll
        for (int j = 0; j < 8; j++) {
            const float bj = best[j];
            const bool pos = 3.0f * bj >= 1.0f;
            const bool neg = 3.5f * bj <  1.0f;
            cnt_p += pos; cnt_n += neg;

            const int y = row0 + rg * 8 + j;
            const int rem = y * H + x;
            const int n = a * HH + rem;
            const float* base = p + (((long)b * 3 + a) * 8) * (long)HH + rem;

            const float o = base[(long)4 * HH];
            const float bce = fmaxf(o, 0.f) - (pos ? o : 0.f) + __logf(1.0f + __expf(-fabsf(o)));

            g_bce[(long)b * NA0 + n] = neg ? bce : -1.0f;
            if (neg) atomicAdd(&s_h[(int)(__float_as_uint(bce) >> 20)], 1);

            if (pos) {
                int gi = 0; float bb = -1.f;
                #pragma unroll
                for (int g = 0; g < 16; g++) {
                    float sc = s_iwS[g * H + x] * s_ih[g * 16 + rg * 8 + j];
                    if (sc > bb) { bb = sc; gi = g; }
                }
                atomicAdd(&z_pb, bce);
                float cxA = (x + 0.5f) * 2.0f, cyA = (y + 0.5f) * 2.0f;
                float ax1 = (cxA - h2) * INV224, ay1 = (cyA - h2) * INV224;
                float ax2 = (cxA + h2) * INV224, ay2 = (cyA + h2) * INV224;
                float aw = ax2 - ax1, ah = ay2 - ay1;
                float mx1 = stb0[gi * 4 + 0], my1 = stb0[gi * 4 + 1];
                float mx2 = stb0[gi * 4 + 2], my2 = stb0[gi * 4 + 3];
                float gcx = 0.5f * (mx1 + mx2), gcy = 0.5f * (my1 + my2);
                float gw = mx2 - mx1, gh = my2 - my1;
                float acx = 0.5f * (ax1 + ax2), acy = 0.5f * (ay1 + ay2);
                float e0 = __fdividef(gcx - acx, aw);
                float e1 = __fdividef(gcy - acy, ah);
                float e2 = __logf(__fdividef(gw, aw) + 1e-6f);
                float e3 = __logf(__fdividef(gh, ah) + 1e-6f);
                float d0 = base[0]            - e0;
                float d1 = base[(long)1 * HH] - e1;
                float d2 = base[(long)2 * HH] - e2;
                float d3 = base[(long)3 * HH] - e3;
                #define SL1_(d) (fabsf(d) < 1.f ? 0.5f * (d) * (d) : fabsf(d) - 0.5f)
                atomicAdd(&z_lo, SL1_(d0) + SL1_(d1) + SL1_(d2) + SL1_(d3));
                #undef SL1_
                float zv0 = base[(long)5 * HH];
                float zv1 = base[(long)6 * HH];
                float zv2 = base[(long)7 * HH];
                float m = fmaxf(zv0, fmaxf(zv1, zv2));
                float lse = m + __logf(__expf(zv0 - m) + __expf(zv1 - m) + __expf(zv2 - m));
                int ml = stl0[gi];
                float zl = (ml == 1) ? zv0 : ((ml == 2) ? zv1 : zv2);
                atomicAdd(&z_cl, lse - zl);
            }
        }
    }

    unsigned wp = __reduce_add_sync(0xffffffff, (unsigned)cnt_p);
    unsigned wn = __reduce_add_sync(0xffffffff, (unsigned)cnt_n);
    if ((t & 31) == 0) {
        if (wp) atomicAdd(&z_np, (int)wp);
        if (wn) atomicAdd(&z_nv, (int)wn);
    }
    __syncthreads();
    flush_block(s_h, &g_hist[b * 2048], b, z_np, z_nv, z_pb, z_cl, z_lo, t);
}

// ---------------- Phase A: generic path (scales 1,2), analytic anchors ----------------

template<int H, int NA, int ACCB, long SCRB, int SB_, int SS_>
__device__ __forceinline__ void phaseA_impl(const float* __restrict__ p,
                                            const float* __restrict__ tb,
                                            const int*   __restrict__ tl,
                                            int bs, int b, int* s_h)
{
    constexpr int HH = H * H;
    constexpr float STRIDE = 224.0f / H;
    __shared__ float stb[NG * 4];
    __shared__ float sarea[NG];
    __shared__ int   stl[NG];
    __shared__ float s_pb, s_cl, s_lo;
    __shared__ int   s_np, s_nv;

    const int t = threadIdx.x;
    if (t < NG * 4) stb[t] = tb[b * NG * 4 + t] * INV224;
    if (t < NG)     stl[t] = tl[b * NG + t];
    if (t == 0) { s_pb = 0.f; s_cl = 0.f; s_lo = 0.f; s_np = 0; s_nv = 0; }
    #pragma unroll
    for (int i = 0; i < 8; i++) s_h[t + i * 256] = 0;
    __syncthreads();
    if (t < NG) sarea[t] = (stb[t * 4 + 2] - stb[t * 4 + 0]) * (stb[t * 4 + 3] - stb[t * 4 + 1]);
    __syncthreads();

    const int n0 = bs * 1024 + t;

    float ax1[4], ay1[4], ax2[4], ay2[4], area[4];
    bool  act[4];
    #pragma unroll
    for (int j = 0; j < 4; j++) {
        const int n = n0 + j * 256;
        act[j] = (n < NA);
        if (act[j]) {
            const int a = n / HH;
            const int rem = n - a * HH;
            const int y = rem / H, x = rem - y * H;
            const float szf = (float)SB_ + (float)SS_ * (float)a;
            const float h2 = 0.5f * szf;
            const float cx = (x + 0.5f) * STRIDE, cy = (y + 0.5f) * STRIDE;
            ax1[j] = (cx - h2) * INV224; ay1[j] = (cy - h2) * INV224;
            ax2[j] = (cx + h2) * INV224; ay2[j] = (cy + h2) * INV224;
            area[j] = (ax2[j] - ax1[j]) * (ay2[j] - ay1[j]);
        } else {
            ax1[j] = 0.f; ay1[j] = 0.f; ax2[j] = 0.f; ay2[j] = 0.f; area[j] = 0.f;
        }
    }

    float bestI[4], bestD[4]; int bi[4];
    #pragma unroll
    for (int j = 0; j < 4; j++) { bestI[j] = -1.f; bestD[j] = 1.f; bi[j] = 0; }

    #pragma unroll
    for (int g = 0; g < NG; g++) {
        const float bx1 = stb[g * 4 + 0], by1 = stb[g * 4 + 1];
        const float bx2 = stb[g * 4 + 2], by2 = stb[g * 4 + 3];
        const float ba  = sarea[g];
        #pragma unroll
        for (int j = 0; j < 4; j++) {
            float lx = fmaxf(ax1[j], bx1), ly = fmaxf(ay1[j], by1);
            float rx = fminf(ax2[j], bx2), ry = fminf(ay2[j], by2);
            float iw = fmaxf(rx - lx, 0.f), ih = fmaxf(ry - ly, 0.f);
            float inter = iw * ih;
            float den = area[j] + ba - inter + 1e-9f;
            if (inter * bestD[j] > bestI[j] * den) { bestI[j] = inter; bestD[j] = den; bi[j] = g; }
        }
    }

    int cnt_p = 0, cnt_n = 0;

    #pragma unroll
    for (int j = 0; j < 4; j++) {
        const int n = n0 + j * 256;
        if (act[j]) {
            const bool pos = bestI[j] >= 0.5f * bestD[j];
            const bool neg = bestI[j] <  0.4f * bestD[j];
            cnt_p += pos; cnt_n += neg;

            const int a = n / HH;
            const int rem = n - a * HH;
            const float* base = p + (((long)b * 3 + a) * 8) * (long)HH + rem;

            const float o = base[(long)4 * HH];
            const float bce = fmaxf(o, 0.f) - (pos ? o : 0.f) + __logf(1.0f + __expf(-fabsf(o)));

            g_bce[SCRB + (long)b * NA + n] = neg ? bce : -1.0f;
            if (neg) atomicAdd(&s_h[(int)(__float_as_uint(bce) >> 20)], 1);

            if (pos) {
                atomicAdd(&s_pb, bce);
                const int gi = bi[j];
                float mx1 = stb[gi * 4 + 0], my1 = stb[gi * 4 + 1];
                float mx2 = stb[gi * 4 + 2], my2 = stb[gi * 4 + 3];
                float gcx = 0.5f * (mx1 + mx2), gcy = 0.5f * (my1 + my2);
                float gw = mx2 - mx1, gh = my2 - my1;
                float aw = ax2[j] - ax1[j], ah = ay2[j] - ay1[j];
                float acx = 0.5f * (ax1[j] + ax2[j]), acy = 0.5f * (ay1[j] + ay2[j]);
                float e0 = __fdividef(gcx - acx, aw);
                float e1 = __fdividef(gcy - acy, ah);
                float e2 = __logf(__fdividef(gw, aw) + 1e-6f);
                float e3 = __logf(__fdividef(gh, ah) + 1e-6f);
                float d0 = base[0]            - e0;
                float d1 = base[(long)1 * HH] - e1;
                float d2 = base[(long)2 * HH] - e2;
                float d3 = base[(long)3 * HH] - e3;
                #define SL1_(d) (fabsf(d) < 1.f ? 0.5f * (d) * (d) : fabsf(d) - 0.5f)
                atomicAdd(&s_lo, SL1_(d0) + SL1_(d1) + SL1_(d2) + SL1_(d3));
                #undef SL1_
                float z0 = base[(long)5 * HH];
                float z1 = base[(long)6 * HH];
                float z2 = base[(long)7 * HH];
                float m = fmaxf(z0, fmaxf(z1, z2));
                float lse = m + __logf(__expf(z0 - m) + __expf(z1 - m) + __expf(z2 - m));
                int ml = stl[gi];
                float zl = (ml == 1) ? z0 : ((ml == 2) ? z1 : z2);
                atomicAdd(&s_cl, lse - zl);
            }
        }
    }

    unsigned wp = __reduce_add_sync(0xffffffff, (unsigned)cnt_p);
    unsigned wn = __reduce_add_sync(0xffffffff, (unsigned)cnt_n);
    if ((t & 31) == 0) {
        if (wp) atomicAdd(&s_np, (int)wp);
        if (wn) atomicAdd(&s_nv, (int)wn);
    }
    __syncthreads();
    flush_block(s_h, &g_hist[(ACCB + b) * 2048], ACCB + b, s_np, s_nv, s_pb, s_cl, s_lo, t);
}

__global__ void __launch_bounds__(256) k_phaseA(const float* __restrict__ p0,
                                                const float* __restrict__ p1,
                                                const float* __restrict__ p2,
                                                const float* __restrict__ tb,
                                                const int*   __restrict__ tl)
{
    __shared__ int s_h[2048];
    const int bx = blockIdx.x, b = blockIdx.y;
    if (bx < NBX0)             scale0_path(p0, tb, tl, bx, b, s_h);
    else if (bx < NBX0 + NBa1) phaseA_impl<56, NA1, 64,  2408448L, 48, 16>(p1, tb, tl, bx - NBX0, b, s_h);
    else                       phaseA_impl<28, NA2, 128, 3010560L, 96, 32>(p2, tb, tl, bx - NBX0 - NBa1, b, s_h);
}

// ---------------- Phase B: cooperative multi-block selection (smem gather) ----------------

__device__ __forceinline__ void select1024(const int* hist, int k, int t, int lane,
                                           int wid, int* s_w, int* sT, int* sKr)
{
    int c = hist[1023 - t];
    int v = c;
    #pragma unroll
    for (int o = 1; o < 32; o <<= 1) { int u = __shfl_up_sync(~0u, v, o); if (lane >= o) v += u; }
    if (lane == 31) s_w[wid] = v;
    __syncthreads();
    if (wid == 0) {
        int w = s_w[lane];
        #pragma unroll
        for (int o = 1; o < 32; o <<= 1) { int u = __shfl_up_sync(~0u, w, o); if (lane >= o) w += u; }
        s_w[lane] = w;
    }
    __syncthreads();
    int incl = v + (wid ? s_w[wid - 1] : 0);
    int excl = incl - c;
    if (excl < k && k <= incl) { *sT = 1023 - t; *sKr = k - excl; }
    __syncthreads();
}

__global__ void __launch_bounds__(1024) k_phaseB(float* __restrict__ out)
{
    const int bid = blockIdx.x;   // 0..383
    int slice, part, nparts;
    if (bid < 256)      { slice = bid >> 2;        part = bid & 3; nparts = 4; }
    else if (bid < 320) { slice = 64 + bid - 256;  part = 0;       nparts = 1; }
    else                { slice = 128 + bid - 320; part = 0;       nparts = 1; }

    const int scale = slice >> 6;
    const int b = slice & 63;
    const int Na   = (scale == 0) ? NA0 : ((scale == 1) ? NA1 : NA2);
    const long off = ((scale == 0) ? 0L : ((scale == 1) ? 2408448L : 3010560L)) + (long)b * Na;
    const int t = threadIdx.x, lane = t & 31, wid = t >> 5;
    const int npos = g_npos[slice];
    const int navail = g_navail[slice];

    __shared__ int   s_w[32];
    __shared__ float s_fw[32];
    __shared__ int   s_hist[1024];
    __shared__ float s_buf[4096];
    __shared__ int   s_cnt, s_base, sT, sKr, s_last;
    __shared__ float s_extra;

    int* hrow = &g_hist[slice * 2048];
    const int k = min(3 * npos, navail);
    const bool havek = (npos > 0 && navail > 0);

    int T = 0, kr = 0, cT = 0;
    bool fits = false;

    if (havek) {
        // level-1 select over 2048 bins (2 bins/thread, from top)
        int c0 = hrow[2047 - 2 * t];
        int c1 = hrow[2046 - 2 * t];
        int v = c0 + c1;
        #pragma unroll
        for (int o = 1; o < 32; o <<= 1) { int u = __shfl_up_sync(~0u, v, o); if (lane >= o) v += u; }
        if (lane == 31) s_w[wid] = v;
        __syncthreads();
        if (wid == 0) {
            int w = s_w[lane];
            #pragma unroll
            for (int o = 1; o < 32; o <<= 1) { int u = __shfl_up_sync(~0u, w, o); if (lane >= o) w += u; }
            s_w[lane] = w;
        }
        if (t == 0) { s_cnt = 0; s_extra = 0.f; }
        __syncthreads();
        int incl = v + (wid ? s_w[wid - 1] : 0);
        int excl = incl - c0 - c1;
        if (excl < k && k <= incl) {
            if (excl + c0 >= k) { sT = 2047 - 2 * t; sKr = k - excl; }
            else                { sT = 2046 - 2 * t; sKr = k - excl - c0; }
        }
        __syncthreads();
        T = sT; kr = sKr;
        cT = hrow[T];
        fits = (cT <= 4096);

        // scan own part: sum buckets > T; gather bucket-T into SMEM
        const float4* p4 = (const float4*)&g_bce[off];
        const int n4 = Na >> 2;
        const int span = n4 / nparts;
        const int i0 = part * span, i1 = i0 + span;
        float partial = 0.f;
        for (int i = i0 + t; i < i1; i += 1024) {
            float4 q = p4[i];
            #pragma unroll
            for (int c = 0; c < 4; c++) {
                float x = (c == 0) ? q.x : (c == 1) ? q.y : (c == 2) ? q.z : q.w;
                unsigned u = __float_as_uint(x);
                if ((int)u >= 0) {
                    int bkt = (int)(u >> 20);
                    if (bkt > T) partial += x;
                    else if (bkt == T && fits) { int pb = atomicAdd(&s_cnt, 1); s_buf[pb] = x; }
                }
            }
        }
        // per-block sum -> one global atomic
        #pragma unroll
        for (int o = 16; o; o >>= 1) partial += __shfl_down_sync(~0u, partial, o);
        __syncthreads();
        if (lane == 0) s_fw[wid] = partial;
        __syncthreads();
        if (t == 0) {
            float s = 0.f;
            #pragma unroll
            for (int i = 0; i < 32; i++) s += s_fw[i];
            if (s != 0.f) atomicAdd(&g_psum[slice], s);
            // reserve segment in global buffer with a single atomic
            s_base = s_cnt ? atomicAdd(&g_bcnt[slice], s_cnt) : 0;
        }
        __syncthreads();
        // contiguous flush of gathered elements
        const int cnt = s_cnt, bas = s_base;
        float* gb = &g_buf[slice * 4096];
        for (int i = t; i < cnt; i += 1024) gb[bas + i] = s_buf[i];
    }

    // publish writes, arrive; last part-block continues
    __threadfence();
    __syncthreads();
    if (t == 0) s_last = (atomicAdd(&g_arr[slice], 1) == nparts - 1);
    __syncthreads();
    if (!s_last) return;
    __threadfence();

    float o_val = 0.f;

    if (havek) {
        float partial = 0.f;
        if (fits) {
            // load merged bucket into smem
            const float* gb = &g_buf[slice * 4096];
            for (int i = t; i < cT; i += 1024) s_buf[i] = gb[i];
            __syncthreads();
            if (kr == cT) {
                for (int i = t; i < cT; i += 1024) partial += s_buf[i];
            } else {
                s_hist[t] = 0;
                __syncthreads();
                for (int i = t; i < cT; i += 1024)
                    atomicAdd(&s_hist[(__float_as_uint(s_buf[i]) >> 10) & 1023], 1);
                __syncthreads();
                select1024(s_hist, kr, t, lane, wid, s_w, &sT, &sKr);
                const int T2 = sT; kr = sKr;
                __syncthreads();
                s_hist[t] = 0;
                __syncthreads();
                for (int i = t; i < cT; i += 1024) {
                    unsigned u = __float_as_uint(s_buf[i]);
                    if (((u >> 10) & 1023) == (unsigned)T2) atomicAdd(&s_hist[u & 1023], 1);
                }
                __syncthreads();
                select1024(s_hist, kr, t, lane, wid, s_w, &sT, &sKr);
                const unsigned thrbits = ((unsigned)T << 20) | ((unsigned)T2 << 10) | (unsigned)sT;
                const int krf = sKr;
                __syncthreads();
                for (int i = t; i < cT; i += 1024) {
                    float x = s_buf[i];
                    if (__float_as_uint(x) > thrbits) partial += x;
                }
                if (t == 0) s_extra = (float)krf * __uint_as_float(thrbits);
            }
            if (t == 0) s_extra += g_psum[slice];
        } else {
            // rare fallback: full global rescan (psum ignored; partial rebuilt)
            s_hist[t] = 0;
            __syncthreads();
            for (int i = t; i < Na; i += 1024) {
                unsigned u = __float_as_uint(g_bce[off + i]);
                if ((int)u >= 0 && (int)(u >> 20) == T)
                    atomicAdd(&s_hist[(u >> 10) & 1023], 1);
            }
            __syncthreads();
            select1024(s_hist, kr, t, lane, wid, s_w, &sT, &sKr);
            const int T2 = sT; kr = sKr;
            __syncthreads();
            s_hist[t] = 0;
            __syncthreads();
            const unsigned top22 = ((unsigned)T << 10) | (unsigned)T2;
            for (int i = t; i < Na; i += 1024) {
                unsigned u = __float_as_uint(g_bce[off + i]);
                if ((int)u >= 0 && (u >> 10) == top22)
                    atomicAdd(&s_hist[u & 1023], 1);
            }
            __syncthreads();
            select1024(s_hist, kr, t, lane, wid, s_w, &sT, &sKr);
            const unsigned thrbits = ((unsigned)T << 20) | ((unsigned)T2 << 10) | (unsigned)sT;
            const int krf = sKr;
            __syncthreads();
            partial = 0.f;
            for (int i = t; i < Na; i += 1024) {
                float x = g_bce[off + i];
                unsigned u = __float_as_uint(x);
                if ((int)u >= 0 && u > thrbits) partial += x;
            }
            if (t == 0) s_extra = (float)krf * __uint_as_float(thrbits);
        }

        #pragma unroll
        for (int o = 16; o; o >>= 1) partial += __shfl_down_sync(~0u, partial, o);
        __syncthreads();
        if (lane == 0) s_fw[wid] = partial;
        __syncthreads();
        if (t == 0) {
            float s = s_extra;
            #pragma unroll
            for (int i = 0; i < 32; i++) s += s_fw[i];
            o_val = g_posbce[slice] / (float)npos + s / (float)k;
        }
    }

    // cleanup + totals
    hrow[t] = 0;
    hrow[t + 1024] = 0;
    if (t == 0) {
        float c = 0.f, l = 0.f;
        if (npos > 0) {
            c = g_cls[slice] / (float)npos;
            l = g_loc[slice] / (4.0f * (float)npos);
        }
        g_npos[slice] = 0; g_navail[slice] = 0;
        g_posbce[slice] = 0.f; g_cls[slice] = 0.f; g_loc[slice] = 0.f;
        g_psum[slice] = 0.f; g_bcnt[slice] = 0; g_arr[slice] = 0;
        atomicAdd(&g_tot[0], o_val);
        atomicAdd(&g_tot[1], c);
        atomicAdd(&g_tot[2], l);
        __threadfence();
        int done = atomicAdd(&g_done, 1);
        if (done == 191) {
            __threadfence();
            float oo = g_tot[0] / (float)NBATCH;
            float cc = g_tot[1] / (float)NBATCH;
            float ll = g_tot[2] / (float)NBATCH;
            out[0] = oo; out[1] = cc; out[2] = ll; out[3] = oo + cc + ll;
            g_tot[0] = 0.f; g_tot[1] = 0.f; g_tot[2] = 0.f;
            g_done = 0;
        }
    }
}

extern "C" void kernel_launch(void* const* d_in, const int* in_sizes, int n_in,
                              void* d_out, int out_size)
{
    const float* p0 = (const float*)d_in[0];
    const float* p1 = (const float*)d_in[1];
    const float* p2 = (const float*)d_in[2];
    const float* tb = (const float*)d_in[6];
    const int*   tl = (const int*)  d_in[7];

    dim3 gA(NBX0 + NBa1 + NBa2, NBATCH);
    k_phaseA<<<gA, 256>>>(p0, p1, p2, tb, tl);
    k_phaseB<<<384, 1024>>>((float*)d_out);
}